// round 8
// baseline (speedup 1.0000x reference)
#include <cuda_runtime.h>
#include <cuda_bf16.h>
#include <cstdint>

#define NB_B 4096
#define ND 16
#define NM 4
#define NR 2048
#define NC 10
#define NDP1 17
#define MU 8.5f
#define LOG2E 1.4426950408889634f

typedef unsigned long long ull;

// Scratch (device globals are the allowed scratch mechanism)
__device__ float g_W[33 * NR];          // k-major: W[k][r]; k<16: A, k<32: B, k=32: G
__device__ float g_psum[16 * NB_B];     // per-rule-block partial batch sums
__device__ uint4 g_consA[NR / 2];       // bf16x2 cons planes, pair-interleaved
__device__ uint4 g_consB[NR / 2];
__device__ uint2 g_consC[NR / 2];
__device__ float g_f[(size_t)NB_B * NR];  // unnormalized f (also norm fallback)

__device__ __forceinline__ ull pack2(float x, float y) {
    ull r;
    asm("mov.b64 %0, {%1, %2};" : "=l"(r) : "f"(x), "f"(y));
    return r;
}
__device__ __forceinline__ void unpack2(float& x, float& y, ull v) {
    asm("mov.b64 {%0, %1}, %2;" : "=f"(x), "=f"(y) : "l"(v));
}
__device__ __forceinline__ void ffma2(ull& d, ull a, ull b) {
    asm("fma.rn.f32x2 %0, %1, %2, %0;" : "+l"(d) : "l"(a), "l"(b));
}
__device__ __forceinline__ float ex2(float s) {
    float r;
    asm("ex2.approx.ftz.f32 %0, %1;" : "=f"(r) : "f"(s));
    return r;
}

// ---------------------------------------------------------------------------
// K0: warp per rule. Quadratic-form coefficients (fp32) + bf16 cons planes.
// ---------------------------------------------------------------------------
__global__ __launch_bounds__(256) void prep_kernel(
    const float* __restrict__ cons, const int* __restrict__ rules,
    const float* __restrict__ centers, const float* __restrict__ widths) {
    const int gw   = (blockIdx.x * 256 + threadIdx.x) >> 5;  // rule id
    const int lane = threadIdx.x & 31;
    if (gw >= NR) return;

    // consequent column sums via shuffle tree
    float s[NC];
#pragma unroll
    for (int c = 0; c < NC; ++c) s[c] = 0.f;
    if (lane < NDP1) {
        const float* row = cons + (size_t)gw * NDP1 * NC + lane * NC;
#pragma unroll
        for (int c = 0; c < NC; ++c) s[c] = row[c];
    }
#pragma unroll
    for (int off = 16; off > 0; off >>= 1)
#pragma unroll
        for (int c = 0; c < NC; ++c)
            s[c] += __shfl_xor_sync(0xffffffffu, s[c], off);

    // quadratic coefficients: log2(mf) = A x^2 + B x + C
    float Cc = 0.f;
    if (lane < ND) {
        int   m  = rules[gw * ND + lane];
        float c  = centers[lane * NM + m];
        float wd = widths[lane * NM + m];
        float A  = -0.5f * LOG2E / (wd * wd);
        float Bq = -2.f * c * A;
        Cc = A * c * c;
        g_W[lane * NR + gw]        = A;
        g_W[(16 + lane) * NR + gw] = Bq;
    }
#pragma unroll
    for (int off = 16; off > 0; off >>= 1)
        Cc += __shfl_xor_sync(0xffffffffu, Cc, off);

    if (lane == 0) {
        g_W[32 * NR + gw] = Cc;
        const int q = gw >> 1, r1 = gw & 1;
        unsigned wbits[5];
#pragma unroll
        for (int p = 0; p < 5; ++p) {
            __nv_bfloat162 h =
                __floats2bfloat162_rn(s[2 * p] - MU, s[2 * p + 1] - MU);
            wbits[p] = *(unsigned*)&h;
        }
        ((unsigned*)g_consA)[q * 4 + 0 + r1] = wbits[0];
        ((unsigned*)g_consA)[q * 4 + 2 + r1] = wbits[1];
        ((unsigned*)g_consB)[q * 4 + 0 + r1] = wbits[2];
        ((unsigned*)g_consB)[q * 4 + 2 + r1] = wbits[3];
        ((unsigned*)g_consC)[q * 2 + r1]     = wbits[4];
    }
}

// ---------------------------------------------------------------------------
// K1: S = W(2048x33) . [x^2; x; 1](33xB) as a register-blocked GEMM.
// Block tile: 128 rules x 64 batches; thread tile 4 rules x 4 batch-pairs
// (packed f32x2). Epilogue: f = exp2(s), STG unnormalized f, per-block
// batch sums -> g_psum (deterministic, no atomics).
// ---------------------------------------------------------------------------
__global__ __launch_bounds__(256, 3) void gemm_kernel(
    const float* __restrict__ x, float* __restrict__ f_out) {
    __shared__ __align__(16) ull  sWd[33 * 128];   // W duplicated (w,w)
    __shared__ __align__(16) ull  sXp[33 * 32];    // X packed (even,odd batch)
    __shared__ float sxr[64 * 17];                 // padded raw x
    __shared__ float sred[8 * 64];                 // warp-partial batch sums

    const int tid  = threadIdx.x;
    const int w    = tid >> 5;
    const int lane = tid & 31;
    const int b0     = blockIdx.x * 64;
    const int r_base = blockIdx.y * 128;

    for (int i = tid; i < 33 * 128; i += 256) {
        int k = i >> 7, r = i & 127;
        float wv = g_W[k * NR + r_base + r];
        sWd[i] = pack2(wv, wv);
    }
    for (int i = tid; i < 64 * ND; i += 256) {
        int b = i >> 4, d = i & 15;
        sxr[b * 17 + d] = x[(b0 + b) * ND + d];
    }
    __syncthreads();
    for (int i = tid; i < 33 * 32; i += 256) {
        int k = i >> 5, p = i & 31;
        float x0, x1;
        if (k < 16) {
            x0 = sxr[(2 * p) * 17 + k];
            x1 = sxr[(2 * p + 1) * 17 + k];
            x0 *= x0; x1 *= x1;
        } else if (k < 32) {
            x0 = sxr[(2 * p) * 17 + k - 16];
            x1 = sxr[(2 * p + 1) * 17 + k - 16];
        } else {
            x0 = 1.f; x1 = 1.f;
        }
        sXp[k * 32 + p] = pack2(x0, x1);
    }
    __syncthreads();

    const int ri = tid >> 3;     // 0..31 rule group (4 rules each)
    const int bi = tid & 7;      // 0..7 batch-pair group (4 pairs each)

    ull acc[4][4];
#pragma unroll
    for (int i = 0; i < 4; ++i)
#pragma unroll
        for (int j = 0; j < 4; ++j) acc[i][j] = 0ull;

    const ulonglong2* Wp = reinterpret_cast<const ulonglong2*>(sWd) + ri * 2;
    const ulonglong2* Xp = reinterpret_cast<const ulonglong2*>(sXp) + bi * 2;

#pragma unroll
    for (int k = 0; k < 33; ++k) {
        ulonglong2 wA = Wp[k * 64];
        ulonglong2 wB = Wp[k * 64 + 1];
        ulonglong2 xA = Xp[k * 16];
        ulonglong2 xB = Xp[k * 16 + 1];
        const ull wv[4] = {wA.x, wA.y, wB.x, wB.y};
        const ull xv[4] = {xA.x, xA.y, xB.x, xB.y};
#pragma unroll
        for (int i = 0; i < 4; ++i)
#pragma unroll
            for (int j = 0; j < 4; ++j)
                ffma2(acc[i][j], wv[i], xv[j]);
    }

    // epilogue: exp, store f, batch sums
    float bse[4], bso[4];
#pragma unroll
    for (int j = 0; j < 4; ++j) {
        float fe[4], fo[4];
#pragma unroll
        for (int i = 0; i < 4; ++i) {
            float se, so;
            unpack2(se, so, acc[i][j]);
            fe[i] = ex2(se);
            fo[i] = ex2(so);
        }
        const int be = b0 + (bi * 4 + j) * 2;
        float4* pe = (float4*)(f_out + (size_t)be * NR + r_base + ri * 4);
        float4* po = (float4*)(f_out + (size_t)(be + 1) * NR + r_base + ri * 4);
        *pe = make_float4(fe[0], fe[1], fe[2], fe[3]);
        *po = make_float4(fo[0], fo[1], fo[2], fo[3]);
        bse[j] = (fe[0] + fe[1]) + (fe[2] + fe[3]);
        bso[j] = (fo[0] + fo[1]) + (fo[2] + fo[3]);
    }
#pragma unroll
    for (int j = 0; j < 4; ++j) {
        bse[j] += __shfl_xor_sync(0xffffffffu, bse[j], 8);
        bso[j] += __shfl_xor_sync(0xffffffffu, bso[j], 8);
        bse[j] += __shfl_xor_sync(0xffffffffu, bse[j], 16);
        bso[j] += __shfl_xor_sync(0xffffffffu, bso[j], 16);
    }
    if (lane < 8) {
#pragma unroll
        for (int j = 0; j < 4; ++j) {
            sred[w * 64 + (lane * 4 + j) * 2]     = bse[j];
            sred[w * 64 + (lane * 4 + j) * 2 + 1] = bso[j];
        }
    }
    __syncthreads();
    if (tid < 64) {
        float ssum = 0.f;
#pragma unroll
        for (int wi = 0; wi < 8; ++wi) ssum += sred[wi * 64 + tid];
        g_psum[blockIdx.y * NB_B + b0 + tid] = ssum;
    }
}

// ---------------------------------------------------------------------------
// K2: block per batch. inv from partials; normalize f -> norm_fs; GEMV with
// L1-hot bf16 cons planes; out and x_ext.
// ---------------------------------------------------------------------------
__global__ __launch_bounds__(256) void finalize_kernel(
    const float* __restrict__ x,
    const float* __restrict__ f_in,
    float* __restrict__ norm_out,
    float* __restrict__ xext_out,
    float* __restrict__ out,
    int write_xext) {
    __shared__ float sA[16], sB[16], sv[3];   // partials, x, {tot, inv, sx}
    __shared__ float sred2[8][NC];

    const int b    = blockIdx.x;
    const int tid  = threadIdx.x;
    const int w    = tid >> 5;
    const int lane = tid & 31;

    if (tid < 16) {
        sA[tid] = g_psum[tid * NB_B + b];
        float xv = x[b * ND + tid];
        sB[tid] = xv;
        if (write_xext) xext_out[b * NDP1 + tid] = xv;
    }
    if (tid == 16 && write_xext) xext_out[b * NDP1 + ND] = 1.f;
    __syncthreads();
    if (tid == 0) {
        float t = 0.f, sx = 1.f;
#pragma unroll
        for (int i = 0; i < 16; ++i) { t += sA[i]; sx += sB[i]; }
        sv[0] = t;
        sv[1] = 1.f / (t + 1e-9f);
        sv[2] = sx;
    }
    __syncthreads();
    const float inv = sv[1];

    float acc[NC];
#pragma unroll
    for (int c = 0; c < NC; ++c) acc[c] = 0.f;

#pragma unroll
    for (int chunk = 0; chunk < 2; ++chunk) {
        const int r0 = chunk * 1024 + tid * 4;
        float4 fv = *(const float4*)(f_in + (size_t)b * NR + r0);
        float fn[4] = {fv.x * inv, fv.y * inv, fv.z * inv, fv.w * inv};
        *(float4*)(norm_out + (size_t)b * NR + r0) =
            make_float4(fn[0], fn[1], fn[2], fn[3]);
        const int q = r0 >> 1;
#pragma unroll
        for (int pq = 0; pq < 2; ++pq) {
            uint4 cA = g_consA[q + pq];
            uint4 cB = g_consB[q + pq];
            uint2 cC = g_consC[q + pq];
            const unsigned we[5] = {cA.x, cA.z, cB.x, cB.z, cC.x};
            const unsigned wo[5] = {cA.y, cA.w, cB.y, cB.w, cC.y};
            const float fE = fn[2 * pq], fO = fn[2 * pq + 1];
#pragma unroll
            for (int p = 0; p < 5; ++p) {
                acc[2 * p] = fmaf(fE, __uint_as_float(we[p] << 16),
                            fmaf(fO, __uint_as_float(wo[p] << 16), acc[2 * p]));
                acc[2 * p + 1] =
                    fmaf(fE, __uint_as_float(we[p] & 0xffff0000u),
                    fmaf(fO, __uint_as_float(wo[p] & 0xffff0000u),
                         acc[2 * p + 1]));
            }
        }
    }
#pragma unroll
    for (int off = 16; off > 0; off >>= 1)
#pragma unroll
        for (int c = 0; c < NC; ++c)
            acc[c] += __shfl_xor_sync(0xffffffffu, acc[c], off);
    if (lane == 0) {
#pragma unroll
        for (int c = 0; c < NC; ++c) sred2[w][c] = acc[c];
    }
    __syncthreads();
    if (tid < NC) {
        float o = 0.f;
#pragma unroll
        for (int wi = 0; wi < 8; ++wi) o += sred2[wi][tid];
        out[(size_t)b * NC + tid] = (o + MU * sv[0] * sv[1]) * sv[2];
    }
}

// ---------------------------------------------------------------------------
extern "C" void kernel_launch(void* const* d_in, const int* in_sizes, int n_in,
                              void* d_out, int out_size) {
    const float* x       = (const float*)d_in[0];
    const float* centers = (const float*)d_in[1];
    const float* widths  = (const float*)d_in[2];
    const float* cons    = (const float*)d_in[3];
    const int*   rules   = (const int*)d_in[4];
    float* out = (float*)d_out;

    const long long TOTAL = (long long)NB_B * NC + (long long)NB_B * NR +
                            (long long)NB_B * NDP1;

    void* fscratch = nullptr;
    cudaGetSymbolAddress(&fscratch, g_f);
    float* f_p = (float*)fscratch;

    float* out_p = out;
    float* norm_p;
    float* xext_p = out;
    int write_xext = 0;

    if ((long long)out_size == TOTAL) {
        norm_p = out + (size_t)NB_B * NC;
        xext_p = out + (size_t)NB_B * NC + (size_t)NB_B * NR;
        write_xext = 1;
    } else {
        norm_p = f_p;   // in-place normalize into scratch
    }

    prep_kernel<<<NR / 8, 256>>>(cons, rules, centers, widths);
    gemm_kernel<<<dim3(NB_B / 64, NR / 128), 256>>>(x, f_p);
    finalize_kernel<<<NB_B, 256>>>(x, f_p, norm_p, xext_p, out_p, write_xext);
}

// round 9
// speedup vs baseline: 2.0774x; 2.0774x over previous
#include <cuda_runtime.h>
#include <cuda_bf16.h>
#include <cstdint>

#define NB_B 4096
#define ND 16
#define NM 4
#define NR 2048
#define NC 10
#define NDP1 17
#define MU 8.5f

typedef unsigned long long ull;

// cons planes, mean-centered bf16x2, laid out per rule-PAIR for LDG.128:
//   g_consA[q] = {p0/even, p0/odd, p1/even, p1/odd}
//   g_consB[q] = {p2/even, p2/odd, p3/even, p3/odd}
//   g_consC[q] = {p4/even, p4/odd}
__device__ uint4    g_consA[NR / 2];
__device__ uint4    g_consB[NR / 2];
__device__ uint2    g_consC[NR / 2];
__device__ unsigned g_rpack[NR];                        // 16 dims x 2 bits
__device__ float    g_inv[NB_B];
__device__ float    g_norm_scratch[(size_t)NB_B * NR];  // fallback only

__device__ __forceinline__ unsigned spread16(unsigned v) {
    v &= 0xFFFFu;
    v = (v | (v << 8)) & 0x00FF00FFu;
    v = (v | (v << 4)) & 0x0F0F0F0Fu;
    v = (v | (v << 2)) & 0x33333333u;
    v = (v | (v << 1)) & 0x55555555u;
    return v;
}

__device__ __forceinline__ ull pack2(float x, float y) {
    ull r;
    asm("mov.b64 %0, {%1, %2};" : "=l"(r) : "f"(x), "f"(y));
    return r;
}
__device__ __forceinline__ void unpack2(float& x, float& y, ull v) {
    asm("mov.b64 {%0, %1}, %2;" : "=f"(x), "=f"(y) : "l"(v));
}
__device__ __forceinline__ void ffma2(ull& d, ull a, ull b) {
    asm("fma.rn.f32x2 %0, %1, %2, %0;" : "+l"(d) : "l"(a), "l"(b));
}

// ---------------------------------------------------------------------------
// K0: warp per rule (R6-proven). Shuffle-tree reduces cons[r,:,c]; lane 0
// writes 5 mean-centered bf16x2 words (pair-interleaved) + packed indices.
// ---------------------------------------------------------------------------
__global__ __launch_bounds__(256) void prep_kernel(
    const float* __restrict__ cons, const int* __restrict__ rules) {
    const int gw   = (blockIdx.x * 256 + threadIdx.x) >> 5;  // rule id
    const int lane = threadIdx.x & 31;
    if (gw >= NR) return;

    float s[NC];
#pragma unroll
    for (int c = 0; c < NC; ++c) s[c] = 0.f;
    if (lane < NDP1) {
        const float* row = cons + (size_t)gw * NDP1 * NC + lane * NC;
#pragma unroll
        for (int c = 0; c < NC; ++c) s[c] = row[c];
    }
#pragma unroll
    for (int off = 16; off > 0; off >>= 1)
#pragma unroll
        for (int c = 0; c < NC; ++c)
            s[c] += __shfl_xor_sync(0xffffffffu, s[c], off);

    int v = (lane < ND) ? rules[gw * ND + lane] : 0;
    unsigned b0 = __ballot_sync(0xffffffffu, v & 1);
    unsigned b1 = __ballot_sync(0xffffffffu, (v >> 1) & 1);

    if (lane == 0) {
        const int q = gw >> 1, r1 = gw & 1;
        unsigned wbits[5];
#pragma unroll
        for (int p = 0; p < 5; ++p) {
            __nv_bfloat162 h =
                __floats2bfloat162_rn(s[2 * p] - MU, s[2 * p + 1] - MU);
            wbits[p] = *(unsigned*)&h;
        }
        ((unsigned*)g_consA)[q * 4 + 0 + r1] = wbits[0];
        ((unsigned*)g_consA)[q * 4 + 2 + r1] = wbits[1];
        ((unsigned*)g_consB)[q * 4 + 0 + r1] = wbits[2];
        ((unsigned*)g_consB)[q * 4 + 2 + r1] = wbits[3];
        ((unsigned*)g_consC)[q * 2 + r1]     = wbits[4];
        g_rpack[gw] = spread16(b0) | (spread16(b1) << 1);
    }
}

// ---------------------------------------------------------------------------
// K1 (fused, pass-1 only): block = 8 warps = 2 batch-pairs x 4 warps;
// 8 k-iters per warp (R6 config). Per k-iter: batch-paired float2 table
// lookups, exp, STG of UNNORMALIZED f, packed plane-pair GEMV accumulate.
// Accumulators die at the loop end -> low regs -> 4 blocks/SM.
// Epilogue: out = (acc + MU*tot)*inv*sx ; g_inv[b] for the scale kernel.
// ---------------------------------------------------------------------------
__global__ __launch_bounds__(256, 4) void fused_kernel(
    const float* __restrict__ x,
    const float* __restrict__ centers,
    const float* __restrict__ widths,
    float* __restrict__ norm_out,
    float* __restrict__ xext_out,
    float* __restrict__ out,
    int write_xext) {
    __shared__ float  s_e[4][64];
    __shared__ float2 s_tab[2][8][16];   // [pair][table][idx] = (eA, eB)
    __shared__ float  s_sum[8][2];
    __shared__ float  s_acc[8][2][NC];
    __shared__ float  s_sx[4];

    const int tid  = threadIdx.x;
    const int w    = tid >> 5;
    const int lane = tid & 31;
    const int g    = w >> 2;        // batch-pair group (0/1)
    const int qw   = w & 3;         // quarter within group
    const int bbase = blockIdx.x * 4;

    // setup: warps 0..3 each handle batch bbase+w (pair = w>>1, half = w&1)
    if (w < 4) {
        const int b = bbase + w;
        float xv = (lane < ND) ? x[b * ND + lane] : 0.f;
        float sx = xv;
#pragma unroll
        for (int off = 16; off > 0; off >>= 1)
            sx += __shfl_xor_sync(0xffffffffu, sx, off);
        sx += 1.f;
        if (lane == 0) s_sx[w] = sx;
        if (write_xext) {
            if (lane < ND) xext_out[b * NDP1 + lane] = xv;
            if (lane == ND) xext_out[b * NDP1 + ND] = 1.f;
        }
#pragma unroll
        for (int k = lane; k < 64; k += 32) {
            int d = k >> 2, m = k & 3;
            float c  = centers[d * NM + m];
            float wd = widths[d * NM + m];
            float xd = __shfl_sync(0xffffffffu, xv, d);
            float dx = xd - c;
            s_e[w][k] = -(dx * dx) / (2.f * wd * wd);
        }
        __syncwarp();
        const int pr = w >> 1, h = w & 1;
#pragma unroll
        for (int k = lane; k < 128; k += 32) {
            int t = k >> 4, i = k & 15;
            float v = s_e[w][(2 * t) * 4 + (i & 3)] +
                      s_e[w][(2 * t + 1) * 4 + (i >> 2)];
            if (h == 0) s_tab[pr][t][i].x = v;
            else        s_tab[pr][t][i].y = v;
        }
    }
    __syncthreads();

    const float2 (*tab)[16] = s_tab[g];
    const uint2* __restrict__ rp = (const uint2*)g_rpack;

    const int bA = bbase + g * 2, bB = bA + 1;
    ull* npA = (ull*)(norm_out + (size_t)bA * NR);
    ull* npB = (ull*)(norm_out + (size_t)bB * NR);

    ull  accA[5], accB[5];               // packed (c=2p, c=2p+1)
    float sumA = 0.f, sumB = 0.f;
#pragma unroll
    for (int p = 0; p < 5; ++p) { accA[p] = 0ull; accB[p] = 0ull; }

#pragma unroll
    for (int k = 0; k < 8; ++k) {
        const int q = (qw * 8 + k) * 32 + lane;   // rule-pair index
        uint2 pp = rp[q];
        float2 v0 = tab[0][pp.x & 15];
        float2 v1 = tab[0][pp.y & 15];
        float s0A = v0.x, s0B = v0.y, s1A = v1.x, s1B = v1.y;
#pragma unroll
        for (int t = 1; t < 8; ++t) {
            float2 a = tab[t][(pp.x >> (4 * t)) & 15];
            float2 b2 = tab[t][(pp.y >> (4 * t)) & 15];
            s0A += a.x;  s0B += a.y;
            s1A += b2.x; s1B += b2.y;
        }
        float f0A = __expf(s0A), f1A = __expf(s1A);
        float f0B = __expf(s0B), f1B = __expf(s1B);
        sumA += f0A + f1A;
        sumB += f0B + f1B;
        npA[q] = pack2(f0A, f1A);                 // UNNORMALIZED f
        npB[q] = pack2(f0B, f1B);

        uint4 cA = g_consA[q];
        uint4 cB = g_consB[q];
        uint2 cC = g_consC[q];
        const unsigned we[5] = {cA.x, cA.z, cB.x, cB.z, cC.x};
        const unsigned wo[5] = {cA.y, cA.w, cB.y, cB.w, cC.y};
        const ull f0A2 = pack2(f0A, f0A), f1A2 = pack2(f1A, f1A);
        const ull f0B2 = pack2(f0B, f0B), f1B2 = pack2(f1B, f1B);
#pragma unroll
        for (int p = 0; p < 5; ++p) {
            ull ce = pack2(__uint_as_float(we[p] << 16),
                           __uint_as_float(we[p] & 0xffff0000u));
            ull co = pack2(__uint_as_float(wo[p] << 16),
                           __uint_as_float(wo[p] & 0xffff0000u));
            ffma2(accA[p], f0A2, ce);
            ffma2(accA[p], f1A2, co);
            ffma2(accB[p], f0B2, ce);
            ffma2(accB[p], f1B2, co);
        }
    }

    // reduce accumulators (they die here)
    float rA[NC], rB[NC];
#pragma unroll
    for (int p = 0; p < 5; ++p) {
        unpack2(rA[2 * p], rA[2 * p + 1], accA[p]);
        unpack2(rB[2 * p], rB[2 * p + 1], accB[p]);
    }
#pragma unroll
    for (int off = 16; off > 0; off >>= 1) {
        sumA += __shfl_xor_sync(0xffffffffu, sumA, off);
        sumB += __shfl_xor_sync(0xffffffffu, sumB, off);
#pragma unroll
        for (int c = 0; c < NC; ++c) {
            rA[c] += __shfl_xor_sync(0xffffffffu, rA[c], off);
            rB[c] += __shfl_xor_sync(0xffffffffu, rB[c], off);
        }
    }
    if (lane == 0) {
        s_sum[w][0] = sumA;
        s_sum[w][1] = sumB;
#pragma unroll
        for (int c = 0; c < NC; ++c) {
            s_acc[w][0][c] = rA[c];
            s_acc[w][1][c] = rB[c];
        }
    }
    __syncthreads();

    if (tid < 4) {                        // g_inv for the scale kernel
        const int gg = tid >> 1, h = tid & 1;
        float tot = s_sum[gg * 4][h] + s_sum[gg * 4 + 1][h] +
                    s_sum[gg * 4 + 2][h] + s_sum[gg * 4 + 3][h];
        g_inv[bbase + gg * 2 + h] = 1.f / (tot + 1e-9f);
    }
    if (tid < 40) {
        const int gg = tid / 20, h = (tid / 10) % 2, c = tid % 10;
        float a = s_acc[gg * 4][h][c] + s_acc[gg * 4 + 1][h][c] +
                  s_acc[gg * 4 + 2][h][c] + s_acc[gg * 4 + 3][h][c];
        float tot = s_sum[gg * 4][h] + s_sum[gg * 4 + 1][h] +
                    s_sum[gg * 4 + 2][h] + s_sum[gg * 4 + 3][h];
        float inv = 1.f / (tot + 1e-9f);
        const int b = bbase + gg * 2 + h;
        out[(size_t)b * NC + c] = (a + MU * tot) * inv * s_sx[gg * 2 + h];
    }
}

// ---------------------------------------------------------------------------
// K2: normalize in place: norm[b][r] *= inv[b]. L2-resident, bandwidth-bound.
// ---------------------------------------------------------------------------
__global__ __launch_bounds__(256) void scale_kernel(float* __restrict__ norm) {
    const int b = blockIdx.x;
    const float inv = g_inv[b];
    float4* p = (float4*)(norm + (size_t)b * NR);
#pragma unroll
    for (int i = threadIdx.x; i < NR / 4; i += 256) {
        float4 v = p[i];
        v.x *= inv; v.y *= inv; v.z *= inv; v.w *= inv;
        p[i] = v;
    }
}

// ---------------------------------------------------------------------------
extern "C" void kernel_launch(void* const* d_in, const int* in_sizes, int n_in,
                              void* d_out, int out_size) {
    const float* x       = (const float*)d_in[0];
    const float* centers = (const float*)d_in[1];
    const float* widths  = (const float*)d_in[2];
    const float* cons    = (const float*)d_in[3];
    const int*   rules   = (const int*)d_in[4];
    float* out = (float*)d_out;

    const long long TOTAL = (long long)NB_B * NC + (long long)NB_B * NR +
                            (long long)NB_B * NDP1;

    float* out_p = out;
    float* norm_p;
    float* xext_p = out;
    int write_xext = 0;

    if ((long long)out_size == TOTAL) {
        norm_p = out + (size_t)NB_B * NC;
        xext_p = out + (size_t)NB_B * NC + (size_t)NB_B * NR;
        write_xext = 1;
    } else {
        void* sp = nullptr;
        cudaGetSymbolAddress(&sp, g_norm_scratch);
        norm_p = (float*)sp;
    }

    prep_kernel<<<NR / 8, 256>>>(cons, rules);
    fused_kernel<<<NB_B / 4, 256>>>(x, centers, widths, norm_p,
                                    xext_p, out_p, write_xext);
    scale_kernel<<<NB_B, 256>>>(norm_p);
}

// round 10
// speedup vs baseline: 2.3308x; 1.1220x over previous
#include <cuda_runtime.h>
#include <cuda_bf16.h>
#include <cstdint>

#define NB_B 4096
#define ND 16
#define NM 4
#define NR 2048
#define NC 10
#define NDP1 17
#define MU 8.5f

typedef unsigned long long ull;

// cons planes, mean-centered bf16x2, pair-interleaved for LDG.128:
//   g_consA[q] = {p0/even, p0/odd, p1/even, p1/odd}
//   g_consB[q] = {p2/even, p2/odd, p3/even, p3/odd}
//   g_consC[q] = {p4/even, p4/odd}
__device__ uint4    g_consA[NR / 2];
__device__ uint4    g_consB[NR / 2];
__device__ uint2    g_consC[NR / 2];
__device__ unsigned g_rpack[NR];                        // 16 dims x 2 bits
__device__ float    g_norm_scratch[(size_t)NB_B * NR];  // fallback only

__device__ __forceinline__ unsigned spread16(unsigned v) {
    v &= 0xFFFFu;
    v = (v | (v << 8)) & 0x00FF00FFu;
    v = (v | (v << 4)) & 0x0F0F0F0Fu;
    v = (v | (v << 2)) & 0x33333333u;
    v = (v | (v << 1)) & 0x55555555u;
    return v;
}

__device__ __forceinline__ ull pack2(float x, float y) {
    ull r;
    asm("mov.b64 %0, {%1, %2};" : "=l"(r) : "f"(x), "f"(y));
    return r;
}
__device__ __forceinline__ void unpack2(float& x, float& y, ull v) {
    asm("mov.b64 {%0, %1}, %2;" : "=f"(x), "=f"(y) : "l"(v));
}
__device__ __forceinline__ void ffma2(ull& d, ull a, ull b) {
    asm("fma.rn.f32x2 %0, %1, %2, %0;" : "+l"(d) : "l"(a), "l"(b));
}
__device__ __forceinline__ ull fmul2(ull a, ull b) {
    ull r;
    asm("mul.rn.f32x2 %0, %1, %2;" : "=l"(r) : "l"(a), "l"(b));
    return r;
}

// ---------------------------------------------------------------------------
// K0: coalesced prep. 128 blocks x 256 thr; 16 rules/block.
// Stage 16x170 floats + 16x16 ints fully coalesced into smem; 80 threads
// compute mean-centered bf16x2 plane-pair sums; 16 threads pack rule indices.
// ---------------------------------------------------------------------------
__global__ __launch_bounds__(256) void prep_kernel(
    const float* __restrict__ cons, const int* __restrict__ rules) {
    __shared__ float sc[16 * NDP1 * NC];   // 10880 B
    __shared__ int   sr[16 * ND];

    const int tid = threadIdx.x;
    const int r0  = blockIdx.x * 16;

    const float* cbase = cons + (size_t)r0 * NDP1 * NC;
#pragma unroll
    for (int i = tid; i < 16 * NDP1 * NC; i += 256) sc[i] = cbase[i];
    sr[tid] = rules[r0 * ND + tid];        // exactly 256 ints
    __syncthreads();

    if (tid < 80) {
        const int rl = tid / 5, p = tid % 5;
        const float* row = sc + rl * NDP1 * NC + 2 * p;
        float s0 = 0.f, s1 = 0.f;
#pragma unroll
        for (int j = 0; j < NDP1; ++j) {
            s0 += row[j * NC];
            s1 += row[j * NC + 1];
        }
        const int gw = r0 + rl, q = gw >> 1, r1 = gw & 1;
        __nv_bfloat162 h = __floats2bfloat162_rn(s0 - MU, s1 - MU);
        unsigned wb = *(unsigned*)&h;
        if (p == 0)      ((unsigned*)g_consA)[q * 4 + 0 + r1] = wb;
        else if (p == 1) ((unsigned*)g_consA)[q * 4 + 2 + r1] = wb;
        else if (p == 2) ((unsigned*)g_consB)[q * 4 + 0 + r1] = wb;
        else if (p == 3) ((unsigned*)g_consB)[q * 4 + 2 + r1] = wb;
        else             ((unsigned*)g_consC)[q * 2 + r1]     = wb;
    } else if (tid < 96) {
        const int rl = tid - 80;
        unsigned pk = 0;
#pragma unroll
        for (int d = 0; d < ND; ++d)
            pk |= ((unsigned)sr[rl * ND + d] & 3u) << (2 * d);
        g_rpack[r0 + rl] = pk;
    }
}

// ---------------------------------------------------------------------------
// K1 (fused): block = 8 warps = 2 batch-pairs x 4 warps; 8 k-iters/warp.
// Pass 1: batch-paired float2 table lookups, exp, park UNNORMALIZED packed f
// in SMEM, packed plane-pair GEMV accumulate (accs die at loop end).
// Block reduce -> inv. Pass 2: LDS f, mul.f32x2 by inv, STG normalized.
// No scale kernel, no f registers.
// ---------------------------------------------------------------------------
__global__ __launch_bounds__(256, 4) void fused_kernel(
    const float* __restrict__ x,
    const float* __restrict__ centers,
    const float* __restrict__ widths,
    float* __restrict__ norm_out,
    float* __restrict__ xext_out,
    float* __restrict__ out,
    int write_xext) {
    __shared__ ull    s_f[2][2][NR / 2];  // [pair-group][half][q] : 32 KB
    __shared__ float  s_e[4][64];
    __shared__ float2 s_tab[2][8][16];    // [pair][table][idx] = (eA, eB)
    __shared__ float  s_sum[8][2];
    __shared__ float  s_acc[8][2][NC];
    __shared__ float  s_sx[4];

    const int tid  = threadIdx.x;
    const int w    = tid >> 5;
    const int lane = tid & 31;
    const int g    = w >> 2;        // batch-pair group (0/1)
    const int qw   = w & 3;         // quarter within group
    const int bbase = blockIdx.x * 4;

    // setup: warps 0..3 each handle batch bbase+w (pair = w>>1, half = w&1)
    if (w < 4) {
        const int b = bbase + w;
        float xv = (lane < ND) ? x[b * ND + lane] : 0.f;
        float sx = xv;
#pragma unroll
        for (int off = 16; off > 0; off >>= 1)
            sx += __shfl_xor_sync(0xffffffffu, sx, off);
        sx += 1.f;
        if (lane == 0) s_sx[w] = sx;
        if (write_xext) {
            if (lane < ND) xext_out[b * NDP1 + lane] = xv;
            if (lane == ND) xext_out[b * NDP1 + ND] = 1.f;
        }
#pragma unroll
        for (int k = lane; k < 64; k += 32) {
            int d = k >> 2, m = k & 3;
            float c  = centers[d * NM + m];
            float wd = widths[d * NM + m];
            float xd = __shfl_sync(0xffffffffu, xv, d);
            float dx = xd - c;
            s_e[w][k] = -(dx * dx) / (2.f * wd * wd);
        }
        __syncwarp();
        const int pr = w >> 1, h = w & 1;
#pragma unroll
        for (int k = lane; k < 128; k += 32) {
            int t = k >> 4, i = k & 15;
            float v = s_e[w][(2 * t) * 4 + (i & 3)] +
                      s_e[w][(2 * t + 1) * 4 + (i >> 2)];
            if (h == 0) s_tab[pr][t][i].x = v;
            else        s_tab[pr][t][i].y = v;
        }
    }
    __syncthreads();

    const float2 (*tab)[16] = s_tab[g];
    const uint2* __restrict__ rp = (const uint2*)g_rpack;

    ull  accA[5], accB[5];               // packed (c=2p, c=2p+1)
    float sumA = 0.f, sumB = 0.f;
#pragma unroll
    for (int p = 0; p < 5; ++p) { accA[p] = 0ull; accB[p] = 0ull; }

#pragma unroll
    for (int k = 0; k < 8; ++k) {
        const int q = (qw * 8 + k) * 32 + lane;   // rule-pair index
        uint2 pp = rp[q];
        float2 v0 = tab[0][pp.x & 15];
        float2 v1 = tab[0][pp.y & 15];
        float s0A = v0.x, s0B = v0.y, s1A = v1.x, s1B = v1.y;
#pragma unroll
        for (int t = 1; t < 8; ++t) {
            float2 a = tab[t][(pp.x >> (4 * t)) & 15];
            float2 b2 = tab[t][(pp.y >> (4 * t)) & 15];
            s0A += a.x;  s0B += a.y;
            s1A += b2.x; s1B += b2.y;
        }
        float f0A = __expf(s0A), f1A = __expf(s1A);
        float f0B = __expf(s0B), f1B = __expf(s1B);
        sumA += f0A + f1A;
        sumB += f0B + f1B;
        s_f[g][0][q] = pack2(f0A, f1A);           // park unnormalized f
        s_f[g][1][q] = pack2(f0B, f1B);

        uint4 cA = g_consA[q];
        uint4 cB = g_consB[q];
        uint2 cC = g_consC[q];
        const unsigned we[5] = {cA.x, cA.z, cB.x, cB.z, cC.x};
        const unsigned wo[5] = {cA.y, cA.w, cB.y, cB.w, cC.y};
        const ull f0A2 = pack2(f0A, f0A), f1A2 = pack2(f1A, f1A);
        const ull f0B2 = pack2(f0B, f0B), f1B2 = pack2(f1B, f1B);
#pragma unroll
        for (int p = 0; p < 5; ++p) {
            ull ce = pack2(__uint_as_float(we[p] << 16),
                           __uint_as_float(we[p] & 0xffff0000u));
            ull co = pack2(__uint_as_float(wo[p] << 16),
                           __uint_as_float(wo[p] & 0xffff0000u));
            ffma2(accA[p], f0A2, ce);
            ffma2(accA[p], f1A2, co);
            ffma2(accB[p], f0B2, ce);
            ffma2(accB[p], f1B2, co);
        }
    }

    // reduce accumulators (they die here)
    float rA[NC], rB[NC];
#pragma unroll
    for (int p = 0; p < 5; ++p) {
        unpack2(rA[2 * p], rA[2 * p + 1], accA[p]);
        unpack2(rB[2 * p], rB[2 * p + 1], accB[p]);
    }
#pragma unroll
    for (int off = 16; off > 0; off >>= 1) {
        sumA += __shfl_xor_sync(0xffffffffu, sumA, off);
        sumB += __shfl_xor_sync(0xffffffffu, sumB, off);
#pragma unroll
        for (int c = 0; c < NC; ++c) {
            rA[c] += __shfl_xor_sync(0xffffffffu, rA[c], off);
            rB[c] += __shfl_xor_sync(0xffffffffu, rB[c], off);
        }
    }
    if (lane == 0) {
        s_sum[w][0] = sumA;
        s_sum[w][1] = sumB;
#pragma unroll
        for (int c = 0; c < NC; ++c) {
            s_acc[w][0][c] = rA[c];
            s_acc[w][1][c] = rB[c];
        }
    }
    __syncthreads();

    const float totA = s_sum[g * 4][0] + s_sum[g * 4 + 1][0] +
                       s_sum[g * 4 + 2][0] + s_sum[g * 4 + 3][0];
    const float totB = s_sum[g * 4][1] + s_sum[g * 4 + 1][1] +
                       s_sum[g * 4 + 2][1] + s_sum[g * 4 + 3][1];
    const float invA = 1.f / (totA + 1e-9f);
    const float invB = 1.f / (totB + 1e-9f);
    const ull invA2 = pack2(invA, invA);
    const ull invB2 = pack2(invB, invB);

    // ---- pass 2: normalized writes from smem-parked f ----
    const int bA = bbase + g * 2, bB = bA + 1;
    ull* npA = (ull*)(norm_out + (size_t)bA * NR);
    ull* npB = (ull*)(norm_out + (size_t)bB * NR);
#pragma unroll
    for (int k = 0; k < 8; ++k) {
        const int q = (qw * 8 + k) * 32 + lane;
        npA[q] = fmul2(s_f[g][0][q], invA2);
        npB[q] = fmul2(s_f[g][1][q], invB2);
    }

    // ---- output ----
    if (tid < 40) {
        const int gg = tid / 20, h = (tid / 10) % 2, c = tid % 10;
        float a = s_acc[gg * 4][h][c] + s_acc[gg * 4 + 1][h][c] +
                  s_acc[gg * 4 + 2][h][c] + s_acc[gg * 4 + 3][h][c];
        float tot = s_sum[gg * 4][h] + s_sum[gg * 4 + 1][h] +
                    s_sum[gg * 4 + 2][h] + s_sum[gg * 4 + 3][h];
        float inv = 1.f / (tot + 1e-9f);
        const int b = bbase + gg * 2 + h;
        out[(size_t)b * NC + c] = (a + MU * tot) * inv * s_sx[gg * 2 + h];
    }
}

// ---------------------------------------------------------------------------
extern "C" void kernel_launch(void* const* d_in, const int* in_sizes, int n_in,
                              void* d_out, int out_size) {
    const float* x       = (const float*)d_in[0];
    const float* centers = (const float*)d_in[1];
    const float* widths  = (const float*)d_in[2];
    const float* cons    = (const float*)d_in[3];
    const int*   rules   = (const int*)d_in[4];
    float* out = (float*)d_out;

    const long long TOTAL = (long long)NB_B * NC + (long long)NB_B * NR +
                            (long long)NB_B * NDP1;

    float* out_p = out;
    float* norm_p;
    float* xext_p = out;
    int write_xext = 0;

    if ((long long)out_size == TOTAL) {
        norm_p = out + (size_t)NB_B * NC;
        xext_p = out + (size_t)NB_B * NC + (size_t)NB_B * NR;
        write_xext = 1;
    } else {
        void* sp = nullptr;
        cudaGetSymbolAddress(&sp, g_norm_scratch);
        norm_p = (float*)sp;
    }

    prep_kernel<<<NR / 16, 256>>>(cons, rules);
    fused_kernel<<<NB_B / 4, 256>>>(x, centers, widths, norm_p,
                                    xext_p, out_p, write_xext);
}